// round 12
// baseline (speedup 1.0000x reference)
#include <cuda_runtime.h>
#include <math.h>

#define N_NODES 8192
#define NB 1184            // persistent CTAs: 148 SMs x 8 CTAs (<= residency)
#define NTHREADS 256
#define CHUNKS 4
#define ROWS_PER_CHUNK (N_NODES / CHUNKS)                         // 2048
#define FLOAT4_PER_CHUNK ((long long)ROWS_PER_CHUNK * N_NODES / 4) // 4M

// Device scratch (no cudaMalloc allowed). Both zeroed per launch via memset
// nodes in the captured graph (keeps the kernel deterministic across replays).
__device__ float    g_rowsum[N_NODES];
__device__ unsigned g_bar;

// ---------------------------------------------------------------------------
// Software grid barrier. Safe ONLY because all NB CTAs are co-resident
// (launch_bounds(256, 8) caps regs at 32 -> 8 CTAs/SM -> 1184 <= capacity).
// ---------------------------------------------------------------------------
__device__ __forceinline__ void grid_barrier(unsigned target) {
    __syncthreads();
    __threadfence();  // release: make this block's stores/atomics visible
    if (threadIdx.x == 0) {
        atomicAdd(&g_bar, 1u);
        while (*(volatile unsigned*)&g_bar < target) __nanosleep(64);
    }
    __syncthreads();
}

// ---------------------------------------------------------------------------
// Zero one 64MB chunk with coalesced float4 stores (default caching so the
// lines stay in L2 for the next phase's scatter atomics).
// ---------------------------------------------------------------------------
__device__ __forceinline__ void zero_chunk(float4* __restrict__ out4, int k,
                                           int worker, int nworkers) {
    long long s = (long long)k * FLOAT4_PER_CHUNK;
    long long e = s + FLOAT4_PER_CHUNK;
    const float4 z = make_float4(0.f, 0.f, 0.f, 0.f);
    for (long long i = s + worker; i < e; i += nworkers)
        out4[i] = z;
}

// ---------------------------------------------------------------------------
// Scatter all edges of one list whose row falls in [rlo, rhi).
// Atomic result unused -> RED.ADD; target lines are L2-hot (just zeroed).
// ---------------------------------------------------------------------------
__device__ __forceinline__ void scatter_range(const int* __restrict__ rows,
                                              const int* __restrict__ cols,
                                              const float* __restrict__ vals,
                                              float w, int E, int rlo, int rhi,
                                              float* __restrict__ out,
                                              int worker, int nworkers) {
    for (int i = worker; i < E; i += nworkers) {
        int r = rows[i];
        if (r >= rlo && r < rhi) {
            float rs = g_rowsum[r];
            rs = (rs == 0.f) ? 1.f : rs;
            atomicAdd(&out[(long long)r * N_NODES + cols[i]],
                      __fdividef(w * vals[i], rs));
        }
    }
}

// ---------------------------------------------------------------------------
// Persistent fused kernel: software-pipelined zero / rowsum / scatter.
//   phase 0 : rowsum (256 blocks)           || zero chunk 0 (928 blocks)
//   phase k : scatter chunk k-1 (160 blocks) || zero chunk k (1024 blocks)
//   phase C : scatter chunk C-1 (all blocks)
// ---------------------------------------------------------------------------
__global__ void __launch_bounds__(NTHREADS, 8)
k_fused(const int* __restrict__ rows_s, const int* __restrict__ cols_s,
        const float* __restrict__ vals_s,
        const int* __restrict__ rows_t, const int* __restrict__ cols_t,
        const float* __restrict__ vals_t,
        const float* __restrict__ gamma, float* __restrict__ out, int E) {
    int b = blockIdx.x;
    int t = threadIdx.x;
    float alpha = 1.0f / (1.0f + __expf(-gamma[0]));
    float4* out4 = (float4*)out;

    // ---- Phase 0: rowsum || zero chunk 0 ----
    const int RB = 256;  // rowsum blocks
    if (b < RB) {
        int worker = b * NTHREADS + t, nw = RB * NTHREADS;
        for (int i = worker; i < E; i += nw)
            atomicAdd(&g_rowsum[rows_s[i]], alpha * vals_s[i]);
        for (int i = worker; i < E; i += nw)
            atomicAdd(&g_rowsum[rows_t[i]], (1.0f - alpha) * vals_t[i]);
    } else {
        int worker = (b - RB) * NTHREADS + t, nw = (NB - RB) * NTHREADS;
        zero_chunk(out4, 0, worker, nw);
    }
    grid_barrier(NB);

    // ---- Phases 1..CHUNKS-1: scatter chunk k-1 || zero chunk k ----
    const int SB = 160;  // scatter blocks
    for (int k = 1; k < CHUNKS; k++) {
        if (b < SB) {
            int worker = b * NTHREADS + t, nw = SB * NTHREADS;
            int rlo = (k - 1) * ROWS_PER_CHUNK, rhi = rlo + ROWS_PER_CHUNK;
            scatter_range(rows_s, cols_s, vals_s, alpha, E, rlo, rhi, out,
                          worker, nw);
            scatter_range(rows_t, cols_t, vals_t, 1.0f - alpha, E, rlo, rhi,
                          out, worker, nw);
        } else {
            int worker = (b - SB) * NTHREADS + t, nw = (NB - SB) * NTHREADS;
            zero_chunk(out4, k, worker, nw);
        }
        grid_barrier((unsigned)(k + 1) * NB);
    }

    // ---- Final phase: everyone scatters the last chunk ----
    {
        int worker = b * NTHREADS + t, nw = NB * NTHREADS;
        int rlo = (CHUNKS - 1) * ROWS_PER_CHUNK, rhi = N_NODES;
        scatter_range(rows_s, cols_s, vals_s, alpha, E, rlo, rhi, out,
                      worker, nw);
        scatter_range(rows_t, cols_t, vals_t, 1.0f - alpha, E, rlo, rhi, out,
                      worker, nw);
    }
}

// ---------------------------------------------------------------------------
// Launcher: memset scratch -> one persistent kernel
// ---------------------------------------------------------------------------
extern "C" void kernel_launch(void* const* d_in, const int* in_sizes, int n_in,
                              void* d_out, int out_size) {
    const int*   rows_s = (const int*)d_in[0];
    const int*   cols_s = (const int*)d_in[1];
    const float* vals_s = (const float*)d_in[2];
    const int*   rows_t = (const int*)d_in[3];
    const int*   cols_t = (const int*)d_in[4];
    const float* vals_t = (const float*)d_in[5];
    const float* gamma  = (const float*)d_in[6];
    float* out = (float*)d_out;

    const int E = in_sizes[0];

    void* rowsum_ptr = nullptr;
    void* bar_ptr = nullptr;
    cudaGetSymbolAddress(&rowsum_ptr, g_rowsum);
    cudaGetSymbolAddress(&bar_ptr, g_bar);
    cudaMemsetAsync(rowsum_ptr, 0, N_NODES * sizeof(float));
    cudaMemsetAsync(bar_ptr, 0, sizeof(unsigned));

    k_fused<<<NB, NTHREADS>>>(rows_s, cols_s, vals_s,
                              rows_t, cols_t, vals_t,
                              gamma, out, E);
}

// round 14
// speedup vs baseline: 1.6140x; 1.6140x over previous
#include <cuda_runtime.h>
#include <math.h>

#define N_NODES 8192
#define NTHREADS 256
#define CHUNKS 8
#define ROWS_PER_CHUNK (N_NODES / CHUNKS)                          // 1024
#define FLOAT4_PER_CHUNK ((long long)ROWS_PER_CHUNK * N_NODES / 4) // 2M

#define RB 512   // rowsum blocks in kernel 0
#define SB 128   // scatter blocks in pipelined kernels
#define ZB 1024  // zero blocks per chunk

// Row-sum scratch (no cudaMalloc allowed). Zeroed via graph memset node.
__device__ float g_rowsum[N_NODES];

// ---------------------------------------------------------------------------
// Zero one 32MB chunk with coalesced float4 stores (default caching so the
// lines are L2-resident for the next launch's scatter atomics).
// ---------------------------------------------------------------------------
__device__ __forceinline__ void zero_chunk(float4* __restrict__ out4, int k,
                                           int worker, int nworkers) {
    long long s = (long long)k * FLOAT4_PER_CHUNK;
    const float4 z = make_float4(0.f, 0.f, 0.f, 0.f);
#pragma unroll
    for (int j = 0; j < (int)(FLOAT4_PER_CHUNK / (ZB * NTHREADS)); j++)
        out4[s + worker + (long long)j * nworkers] = z;
}

// ---------------------------------------------------------------------------
// Scatter edges whose row falls in [rlo, rhi). Atomic result unused -> RED;
// target lines were zeroed by the PREVIOUS launch -> L2 hits.
// ---------------------------------------------------------------------------
__device__ __forceinline__ void scatter_range(const int* __restrict__ rows,
                                              const int* __restrict__ cols,
                                              const float* __restrict__ vals,
                                              float w, int E, int rlo, int rhi,
                                              float* __restrict__ out,
                                              int worker, int nworkers) {
    for (int i = worker; i < E; i += nworkers) {
        int r = __ldg(&rows[i]);
        if (r >= rlo && r < rhi) {
            float rs = g_rowsum[r];
            rs = (rs == 0.f) ? 1.f : rs;
            atomicAdd(&out[(long long)r * N_NODES + __ldg(&cols[i])],
                      __fdividef(w * __ldg(&vals[i]), rs));
        }
    }
}

// ---------------------------------------------------------------------------
// Kernel 0: rowsum (RB blocks) || zero chunk 0 (ZB blocks)
// ---------------------------------------------------------------------------
__global__ void __launch_bounds__(NTHREADS)
k_head(const int* __restrict__ rows_s, const float* __restrict__ vals_s,
       const int* __restrict__ rows_t, const float* __restrict__ vals_t,
       const float* __restrict__ gamma, float* __restrict__ out, int E) {
    int b = blockIdx.x, t = threadIdx.x;
    if (b < RB) {
        float alpha = 1.0f / (1.0f + __expf(-gamma[0]));
        int worker = b * NTHREADS + t, nw = RB * NTHREADS;
        for (int i = worker; i < E; i += nw)
            atomicAdd(&g_rowsum[__ldg(&rows_s[i])], alpha * __ldg(&vals_s[i]));
        for (int i = worker; i < E; i += nw)
            atomicAdd(&g_rowsum[__ldg(&rows_t[i])],
                      (1.0f - alpha) * __ldg(&vals_t[i]));
    } else {
        zero_chunk((float4*)out, 0, (b - RB) * NTHREADS + t, ZB * NTHREADS);
    }
}

// ---------------------------------------------------------------------------
// Kernels 1..CHUNKS-1: scatter chunk k-1 (SB blocks) || zero chunk k (ZB)
// ---------------------------------------------------------------------------
__global__ void __launch_bounds__(NTHREADS)
k_pipe(const int* __restrict__ rows_s, const int* __restrict__ cols_s,
       const float* __restrict__ vals_s,
       const int* __restrict__ rows_t, const int* __restrict__ cols_t,
       const float* __restrict__ vals_t,
       const float* __restrict__ gamma, float* __restrict__ out,
       int E, int k) {
    int b = blockIdx.x, t = threadIdx.x;
    if (b < SB) {
        float alpha = 1.0f / (1.0f + __expf(-gamma[0]));
        int worker = b * NTHREADS + t, nw = SB * NTHREADS;
        int rlo = (k - 1) * ROWS_PER_CHUNK, rhi = rlo + ROWS_PER_CHUNK;
        scatter_range(rows_s, cols_s, vals_s, alpha, E, rlo, rhi, out,
                      worker, nw);
        scatter_range(rows_t, cols_t, vals_t, 1.0f - alpha, E, rlo, rhi, out,
                      worker, nw);
    } else {
        zero_chunk((float4*)out, k, (b - SB) * NTHREADS + t, ZB * NTHREADS);
    }
}

// ---------------------------------------------------------------------------
// Final kernel: scatter the last chunk with the whole grid.
// ---------------------------------------------------------------------------
__global__ void __launch_bounds__(NTHREADS)
k_tail(const int* __restrict__ rows_s, const int* __restrict__ cols_s,
       const float* __restrict__ vals_s,
       const int* __restrict__ rows_t, const int* __restrict__ cols_t,
       const float* __restrict__ vals_t,
       const float* __restrict__ gamma, float* __restrict__ out, int E) {
    int worker = blockIdx.x * NTHREADS + threadIdx.x;
    int nw = gridDim.x * NTHREADS;
    float alpha = 1.0f / (1.0f + __expf(-gamma[0]));
    int rlo = (CHUNKS - 1) * ROWS_PER_CHUNK, rhi = N_NODES;
    scatter_range(rows_s, cols_s, vals_s, alpha, E, rlo, rhi, out, worker, nw);
    scatter_range(rows_t, cols_t, vals_t, 1.0f - alpha, E, rlo, rhi, out,
                  worker, nw);
}

// ---------------------------------------------------------------------------
// Launcher: memset(rowsum) -> head -> 7x pipe -> tail, all on one stream.
// Kernel boundaries provide the zero->scatter ordering per chunk.
// ---------------------------------------------------------------------------
extern "C" void kernel_launch(void* const* d_in, const int* in_sizes, int n_in,
                              void* d_out, int out_size) {
    const int*   rows_s = (const int*)d_in[0];
    const int*   cols_s = (const int*)d_in[1];
    const float* vals_s = (const float*)d_in[2];
    const int*   rows_t = (const int*)d_in[3];
    const int*   cols_t = (const int*)d_in[4];
    const float* vals_t = (const float*)d_in[5];
    const float* gamma  = (const float*)d_in[6];
    float* out = (float*)d_out;

    const int E = in_sizes[0];

    void* rowsum_ptr = nullptr;
    cudaGetSymbolAddress(&rowsum_ptr, g_rowsum);
    cudaMemsetAsync(rowsum_ptr, 0, N_NODES * sizeof(float));

    k_head<<<RB + ZB, NTHREADS>>>(rows_s, vals_s, rows_t, vals_t, gamma,
                                  out, E);
    for (int k = 1; k < CHUNKS; k++) {
        k_pipe<<<SB + ZB, NTHREADS>>>(rows_s, cols_s, vals_s,
                                      rows_t, cols_t, vals_t,
                                      gamma, out, E, k);
    }
    k_tail<<<1024, NTHREADS>>>(rows_s, cols_s, vals_s,
                               rows_t, cols_t, vals_t, gamma, out, E);
}